// round 8
// baseline (speedup 1.0000x reference)
#include <cuda_runtime.h>
#include <cstdint>

// Problem constants (fixed by the reference)
#define NB 4
#define NN 10000
#define NE 160000
#define HH 128
#define FF 32
#define MM 256
#define BN (NB * NN)          // 40000 rows for node projections
#define EBLK 64               // edges per block in edge kernel
#define BLOCKS_PER_BATCH (NE / EBLK)  // 2500

// Expected element counts (for input identification)
#define SZ_HIDDEN (NB * NN * HH)        // 5,120,000
#define SZ_EF     (NB * NE * FF)        // 20,480,000
#define SZ_IDX    (NB * NE)             // 640,000
#define SZ_W      ((FF + 2 * HH) * MM)  // 73,728
#define SZ_B      (MM)                  // 256

// Scratch: per-node projections Ps = h @ W_src, Pt = h @ W_tgt + b
__device__ float g_Ps[(size_t)BN * MM];
__device__ float g_Pt[(size_t)BN * MM];
// Normalized int32 index scratch + dtype flags
__device__ int g_src[SZ_IDX];
__device__ int g_tgt[SZ_IDX];
__device__ int g_is64[2];

// ---------------------------------------------------------------------------
// Zero the (poisoned) output buffer.
// ---------------------------------------------------------------------------
__global__ void zero_kernel(float4* __restrict__ out, int n4) {
    int i = blockIdx.x * blockDim.x + threadIdx.x;
    if (i < n4) out[i] = make_float4(0.f, 0.f, 0.f, 0.f);
}

// ---------------------------------------------------------------------------
// Index dtype detection. Reads only the first 128 int32 words (512 B) —
// in-bounds whether the buffer is int32 (2.56 MB) or int64 (5.12 MB).
// If int64 with values in [0, 10000), every odd word (high half) is zero.
// ---------------------------------------------------------------------------
__global__ void detect_idx_kernel(const int* __restrict__ raw_a,
                                  const int* __restrict__ raw_b) {
    if (threadIdx.x == 0 && blockIdx.x == 0) {
        int oa = 0, ob = 0;
#pragma unroll
        for (int j = 1; j < 128; j += 2) { oa |= raw_a[j]; ob |= raw_b[j]; }
        g_is64[0] = (oa == 0) ? 1 : 0;
        g_is64[1] = (ob == 0) ? 1 : 0;
    }
}

// ---------------------------------------------------------------------------
// Normalize indices to int32 scratch, per the detected dtype.
// ---------------------------------------------------------------------------
template <int WHICH>  // 0 = src, 1 = tgt
__global__ void convert_idx_kernel(const void* __restrict__ raw) {
    int i = blockIdx.x * blockDim.x + threadIdx.x;
    if (i >= SZ_IDX) return;
    int v;
    if (g_is64[WHICH]) v = (int)((const long long*)raw)[i];
    else               v = ((const int*)raw)[i];
    // defensive clamp: any surprise becomes a wrong answer, never a crash
    v = (v < 0) ? 0 : (v >= NN ? NN - 1 : v);
    if (WHICH == 0) g_src[i] = v; else g_tgt[i] = v;
}

// ---------------------------------------------------------------------------
// Node projection GEMM:  P[r, m] = sum_k X[r, k] * W[k, m]  (+ bias[m])
//   X: [BN, 128] (hidden, batch-flattened)   W: 128 rows x 256 cols (row stride 256)
// Tile: 64 rows x 64 cols per block, 256 threads, 4x4 microtile, K-chunks of 16.
// DST=0 -> g_Ps (no bias), DST=1 -> g_Pt (+bias).
// ---------------------------------------------------------------------------
template <int DST>
__global__ __launch_bounds__(256) void node_proj_kernel(
    const float* __restrict__ X,
    const float* __restrict__ W,
    const float* __restrict__ bias)
{
    float* __restrict__ P = (DST == 0) ? g_Ps : g_Pt;

    __shared__ float As[16][64];   // [k][row]
    __shared__ float Bs[16][64];   // [k][col]

    const int rblk = blockIdx.x * 64;
    const int cblk = blockIdx.y * 64;
    const int t  = threadIdx.x;
    const int tx = t & 15;         // column quad (4 cols)
    const int ty = t >> 4;         // row quad (4 rows)

    float acc[4][4];
#pragma unroll
    for (int i = 0; i < 4; i++)
#pragma unroll
        for (int j = 0; j < 4; j++) acc[i][j] = 0.f;

    const int lr = t >> 2;         // 0..63 row to load
    const int lk = (t & 3) * 4;    // k quad within chunk
    const int bk = t >> 4;         // 0..15 k row for B load
    const int bm = (t & 15) * 4;   // col quad for B load

#pragma unroll 1
    for (int k0 = 0; k0 < HH; k0 += 16) {
        // A tile: 64 rows x 16 k
        float4 av = *(const float4*)&X[(size_t)(rblk + lr) * HH + k0 + lk];
        // B tile: 16 k x 64 cols
        float4 bv = *(const float4*)&W[(size_t)(k0 + bk) * MM + cblk + bm];
        __syncthreads();
        As[lk + 0][lr] = av.x; As[lk + 1][lr] = av.y;
        As[lk + 2][lr] = av.z; As[lk + 3][lr] = av.w;
        *(float4*)&Bs[bk][bm] = bv;
        __syncthreads();

#pragma unroll
        for (int k = 0; k < 16; k++) {
            float4 a = *(const float4*)&As[k][ty * 4];
            float4 b = *(const float4*)&Bs[k][tx * 4];
            acc[0][0] += a.x * b.x; acc[0][1] += a.x * b.y; acc[0][2] += a.x * b.z; acc[0][3] += a.x * b.w;
            acc[1][0] += a.y * b.x; acc[1][1] += a.y * b.y; acc[1][2] += a.y * b.z; acc[1][3] += a.y * b.w;
            acc[2][0] += a.z * b.x; acc[2][1] += a.z * b.y; acc[2][2] += a.z * b.z; acc[2][3] += a.z * b.w;
            acc[3][0] += a.w * b.x; acc[3][1] += a.w * b.y; acc[3][2] += a.w * b.z; acc[3][3] += a.w * b.w;
        }
    }

    float4 bvv = make_float4(0.f, 0.f, 0.f, 0.f);
    if (DST == 1) bvv = *(const float4*)&bias[cblk + tx * 4];

#pragma unroll
    for (int i = 0; i < 4; i++) {
        int row = rblk + ty * 4 + i;
        float4 o;
        o.x = acc[i][0] + bvv.x;
        o.y = acc[i][1] + bvv.y;
        o.z = acc[i][2] + bvv.z;
        o.w = acc[i][3] + bvv.w;
        *(float4*)&P[(size_t)row * MM + cblk + tx * 4] = o;
    }
}

// ---------------------------------------------------------------------------
// Edge kernel: per edge e in batch b:
//   msg[m] = relu( ef[e] @ Wf[:, m] + Ps[src][m] + Pt[tgt][m] )
//   out[b, tgt, m] += msg[m]   (vector reduction, 4 floats per red op)
// Block: 256 threads = 4 concurrent edges x 64 threads (4 cols each).
// Each block handles 64 edges of one batch.
// ---------------------------------------------------------------------------
__global__ __launch_bounds__(256) void edge_kernel(
    const float* __restrict__ ef,          // [NB*NE, 32]
    const float* __restrict__ W,           // first 32 rows of W_msg, row stride 256
    float* __restrict__ out)               // [NB*NN, 256]
{
    __shared__ float Wf[FF][MM];           // 32 KB
    __shared__ float efs[EBLK][FF];        // 8 KB
    __shared__ int   src_s[EBLK];
    __shared__ int   tgt_s[EBLK];

    const int t   = threadIdx.x;
    const int blk = blockIdx.x;
    const int b   = blk / BLOCKS_PER_BATCH;
    const int e0  = (blk % BLOCKS_PER_BATCH) * EBLK;
    const long long ebase = (long long)b * NE + e0;

    // Stage Wf (32x256 floats = 2048 float4)
    {
        float4* wsh = (float4*)&Wf[0][0];
        const float4* wg = (const float4*)W;
#pragma unroll
        for (int i = 0; i < 8; i++) wsh[t + 256 * i] = wg[t + 256 * i];
    }
    // Stage edge features (64x32 floats = 512 float4)
    {
#pragma unroll
        for (int it = 0; it < 2; it++) {
            int i = t + 256 * it;
            int r = i >> 3, c = (i & 7) * 4;
            float4 v = *(const float4*)&ef[(ebase + r) * FF + c];
            efs[r][c + 0] = v.x; efs[r][c + 1] = v.y;
            efs[r][c + 2] = v.z; efs[r][c + 3] = v.w;
        }
    }
    // Stage indices (already normalized int32, clamped)
    if (t < EBLK) {
        src_s[t] = g_src[ebase + t];
        tgt_s[t] = g_tgt[ebase + t];
    }
    __syncthreads();

    const int grp = t >> 6;          // which of 4 concurrent edges
    const int m4  = (t & 63) * 4;    // column quad 0..252
    const int nodebase = b * NN;

#pragma unroll 1
    for (int g = 0; g < EBLK / 4; g++) {
        const int e = g * 4 + grp;
        const int s = src_s[e];
        const int d = tgt_s[e];

        float4 acc = make_float4(0.f, 0.f, 0.f, 0.f);
#pragma unroll
        for (int k = 0; k < FF; k++) {
            float a   = efs[e][k];
            float4 w  = *(const float4*)&Wf[k][m4];
            acc.x += a * w.x; acc.y += a * w.y;
            acc.z += a * w.z; acc.w += a * w.w;
        }

        float4 ps = *(const float4*)&g_Ps[(size_t)(nodebase + s) * MM + m4];
        float4 pt = *(const float4*)&g_Pt[(size_t)(nodebase + d) * MM + m4];

        float4 r;
        r.x = fmaxf(acc.x + ps.x + pt.x, 0.f);
        r.y = fmaxf(acc.y + ps.y + pt.y, 0.f);
        r.z = fmaxf(acc.z + ps.z + pt.z, 0.f);
        r.w = fmaxf(acc.w + ps.w + pt.w, 0.f);

        float* op = &out[(size_t)(nodebase + d) * MM + m4];
        asm volatile("red.global.add.v4.f32 [%0], {%1, %2, %3, %4};"
                     :: "l"(op), "f"(r.x), "f"(r.y), "f"(r.z), "f"(r.w)
                     : "memory");
    }
}

// ---------------------------------------------------------------------------
// kernel_launch
// Inputs identified BY ELEMENT COUNT (robust to metadata ordering):
//   hidden f32 = 5,120,000 | edge_features f32 = 20,480,000
//   edge_sources = 640,000 | edge_targets = 640,000 (first/second by order)
//   W_msg f32 = 73,728 | b_msg f32 = 256
// Index dtype (int32 vs int64) detected ON DEVICE.
// Output f32 [4,10000,256].
// ---------------------------------------------------------------------------
extern "C" void kernel_launch(void* const* d_in, const int* in_sizes, int n_in,
                              void* d_out, int out_size) {
    const float* hidden = nullptr;
    const float* ef     = nullptr;
    const void*  srcs   = nullptr;
    const void*  tgts   = nullptr;
    const float* W      = nullptr;
    const float* bmsg   = nullptr;

    for (int i = 0; i < n_in; i++) {
        switch (in_sizes[i]) {
            case SZ_HIDDEN: hidden = (const float*)d_in[i]; break;
            case SZ_EF:     ef     = (const float*)d_in[i]; break;
            case SZ_W:      W      = (const float*)d_in[i]; break;
            case SZ_B:      bmsg   = (const float*)d_in[i]; break;
            case SZ_IDX:
                if (!srcs) srcs = d_in[i];
                else       tgts = d_in[i];
                break;
            default: break;
        }
    }
    float* out = (float*)d_out;

    // 0) detect index dtype + normalize to int32 scratch
    detect_idx_kernel<<<1, 32>>>((const int*)srcs, (const int*)tgts);
    convert_idx_kernel<0><<<(SZ_IDX + 255) / 256, 256>>>(srcs);
    convert_idx_kernel<1><<<(SZ_IDX + 255) / 256, 256>>>(tgts);

    // 1) zero output (poisoned by harness)
    int n4 = out_size / 4;
    zero_kernel<<<(n4 + 255) / 256, 256>>>((float4*)out, n4);

    // 2) node projections: Ps = h @ W[32:160], Pt = h @ W[160:288] + b
    dim3 gA(BN / 64, MM / 64);
    node_proj_kernel<0><<<gA, 256>>>(hidden, W + (size_t)FF * MM,        nullptr);
    node_proj_kernel<1><<<gA, 256>>>(hidden, W + (size_t)(FF + HH) * MM, bmsg);

    // 3) per-edge message + scatter-add
    edge_kernel<<<NB * BLOCKS_PER_BATCH, 256>>>(ef, W, out);
}

// round 9
// speedup vs baseline: 1.8841x; 1.8841x over previous
#include <cuda_runtime.h>
#include <cstdint>

// Problem constants (fixed by the reference)
#define NB 4
#define NN 10000
#define NE 160000
#define HH 128
#define FF 32
#define MM 256
#define BN (NB * NN)          // 40000 rows for node projections
#define EBLK 64               // edges per block in edge kernel
#define BLOCKS_PER_BATCH (NE / EBLK)  // 2500

// Expected element counts (for input identification)
#define SZ_HIDDEN (NB * NN * HH)        // 5,120,000
#define SZ_EF     (NB * NE * FF)        // 20,480,000
#define SZ_IDX    (NB * NE)             // 640,000
#define SZ_W      ((FF + 2 * HH) * MM)  // 73,728
#define SZ_B      (MM)                  // 256

// Scratch: per-node projections Ps = h @ W_src, Pt = h @ W_tgt + b
__device__ float g_Ps[(size_t)BN * MM];
__device__ float g_Pt[(size_t)BN * MM];
// Normalized int32 index scratch + dtype flags
__device__ int g_src[SZ_IDX];
__device__ int g_tgt[SZ_IDX];
__device__ int g_is64[2];

// ---------------------------------------------------------------------------
// Zero the (poisoned) output buffer.
// ---------------------------------------------------------------------------
__global__ void zero_kernel(float4* __restrict__ out, int n4) {
    int i = blockIdx.x * blockDim.x + threadIdx.x;
    if (i < n4) out[i] = make_float4(0.f, 0.f, 0.f, 0.f);
}

// ---------------------------------------------------------------------------
// Index dtype detection. Reads only the first 128 int32 words (512 B) —
// in-bounds whether the buffer is int32 (2.56 MB) or int64 (5.12 MB).
// If int64 with values in [0, 10000), every odd word (high half) is zero.
// ---------------------------------------------------------------------------
__global__ void detect_idx_kernel(const int* __restrict__ raw_a,
                                  const int* __restrict__ raw_b) {
    if (threadIdx.x == 0 && blockIdx.x == 0) {
        int oa = 0, ob = 0;
#pragma unroll
        for (int j = 1; j < 128; j += 2) { oa |= raw_a[j]; ob |= raw_b[j]; }
        g_is64[0] = (oa == 0) ? 1 : 0;
        g_is64[1] = (ob == 0) ? 1 : 0;
    }
}

// ---------------------------------------------------------------------------
// Normalize BOTH index arrays to int32 scratch (single launch).
// ---------------------------------------------------------------------------
__global__ void convert_idx_kernel(const void* __restrict__ raw_src,
                                   const void* __restrict__ raw_tgt) {
    int i = blockIdx.x * blockDim.x + threadIdx.x;
    if (i >= 2 * SZ_IDX) return;
    int which = (i >= SZ_IDX) ? 1 : 0;
    int j = i - which * SZ_IDX;
    const void* raw = which ? raw_tgt : raw_src;
    int v;
    if (g_is64[which]) v = (int)((const long long*)raw)[j];
    else               v = ((const int*)raw)[j];
    // defensive clamp: any surprise becomes a wrong answer, never a crash
    v = (v < 0) ? 0 : (v >= NN ? NN - 1 : v);
    if (which == 0) g_src[j] = v; else g_tgt[j] = v;
}

// ---------------------------------------------------------------------------
// Fused node projection GEMM: computes BOTH
//   Ps[r, m] = sum_k X[r, k] * Ws[k, m]
//   Pt[r, m] = sum_k X[r, k] * Wt[k, m] + bias[m]
// sharing the A (X) tile. Tile: 64 rows x 64 cols, 256 threads, 4x4 microtile.
// Per inner-k: 3 LDS.128 + 32 FFMA — near-ideal issue mix.
// ---------------------------------------------------------------------------
__global__ __launch_bounds__(256) void node_proj_kernel(
    const float* __restrict__ X,
    const float* __restrict__ Ws,
    const float* __restrict__ Wt,
    const float* __restrict__ bias)
{
    __shared__ float As[16][64];   // [k][row]
    __shared__ float Bs[16][64];   // [k][col] for Ws
    __shared__ float Cs[16][64];   // [k][col] for Wt

    const int rblk = blockIdx.x * 64;
    const int cblk = blockIdx.y * 64;
    const int t  = threadIdx.x;
    const int tx = t & 15;         // column quad (4 cols)
    const int ty = t >> 4;         // row quad (4 rows)

    float accB[4][4], accC[4][4];
#pragma unroll
    for (int i = 0; i < 4; i++)
#pragma unroll
        for (int j = 0; j < 4; j++) { accB[i][j] = 0.f; accC[i][j] = 0.f; }

    const int lr = t >> 2;         // 0..63 row to load (A)
    const int lk = (t & 3) * 4;    // k quad within chunk (A)
    const int bk = t >> 4;         // 0..15 k row (B/C)
    const int bm = (t & 15) * 4;   // col quad (B/C)

#pragma unroll 1
    for (int k0 = 0; k0 < HH; k0 += 16) {
        float4 av = *(const float4*)&X[(size_t)(rblk + lr) * HH + k0 + lk];
        float4 bv = *(const float4*)&Ws[(size_t)(k0 + bk) * MM + cblk + bm];
        float4 cv = *(const float4*)&Wt[(size_t)(k0 + bk) * MM + cblk + bm];
        __syncthreads();
        As[lk + 0][lr] = av.x; As[lk + 1][lr] = av.y;
        As[lk + 2][lr] = av.z; As[lk + 3][lr] = av.w;
        *(float4*)&Bs[bk][bm] = bv;
        *(float4*)&Cs[bk][bm] = cv;
        __syncthreads();

#pragma unroll
        for (int k = 0; k < 16; k++) {
            float4 a = *(const float4*)&As[k][ty * 4];
            float4 b = *(const float4*)&Bs[k][tx * 4];
            float4 c = *(const float4*)&Cs[k][tx * 4];
            accB[0][0] += a.x * b.x; accB[0][1] += a.x * b.y; accB[0][2] += a.x * b.z; accB[0][3] += a.x * b.w;
            accB[1][0] += a.y * b.x; accB[1][1] += a.y * b.y; accB[1][2] += a.y * b.z; accB[1][3] += a.y * b.w;
            accB[2][0] += a.z * b.x; accB[2][1] += a.z * b.y; accB[2][2] += a.z * b.z; accB[2][3] += a.z * b.w;
            accB[3][0] += a.w * b.x; accB[3][1] += a.w * b.y; accB[3][2] += a.w * b.z; accB[3][3] += a.w * b.w;
            accC[0][0] += a.x * c.x; accC[0][1] += a.x * c.y; accC[0][2] += a.x * c.z; accC[0][3] += a.x * c.w;
            accC[1][0] += a.y * c.x; accC[1][1] += a.y * c.y; accC[1][2] += a.y * c.z; accC[1][3] += a.y * c.w;
            accC[2][0] += a.z * c.x; accC[2][1] += a.z * c.y; accC[2][2] += a.z * c.z; accC[2][3] += a.z * c.w;
            accC[3][0] += a.w * c.x; accC[3][1] += a.w * c.y; accC[3][2] += a.w * c.z; accC[3][3] += a.w * c.w;
        }
    }

    float4 bvv = *(const float4*)&bias[cblk + tx * 4];

#pragma unroll
    for (int i = 0; i < 4; i++) {
        int row = rblk + ty * 4 + i;
        float4 o1, o2;
        o1.x = accB[i][0]; o1.y = accB[i][1]; o1.z = accB[i][2]; o1.w = accB[i][3];
        o2.x = accC[i][0] + bvv.x;
        o2.y = accC[i][1] + bvv.y;
        o2.z = accC[i][2] + bvv.z;
        o2.w = accC[i][3] + bvv.w;
        *(float4*)&g_Ps[(size_t)row * MM + cblk + tx * 4] = o1;
        *(float4*)&g_Pt[(size_t)row * MM + cblk + tx * 4] = o2;
    }
}

// ---------------------------------------------------------------------------
// Edge kernel (edge-quad microtile): per thread, 4 edges x 4 cols.
// Edge features staged TRANSPOSED in smem so one LDS.128 fetches 4 edges'
// k-values -> inner loop is 2 LDS.128 + 16 FFMA per k (1.125x ideal issue).
// Epilogue per edge: coalesced gathers of Ps[src]/Pt[tgt] + relu +
// red.global.add.v4.f32 scatter.
// ---------------------------------------------------------------------------
__global__ __launch_bounds__(256) void edge_kernel(
    const float* __restrict__ ef,          // [NB*NE, 32]
    const float* __restrict__ W,           // first 32 rows of W_msg, row stride 256
    float* __restrict__ out)               // [NB*NN, 256]
{
    __shared__ float Wf[FF][MM];            // 32 KB
    __shared__ float efs_t[FF][EBLK + 4];   // [k][edge], padded for alignment
    __shared__ int   src_s[EBLK];
    __shared__ int   tgt_s[EBLK];

    const int t   = threadIdx.x;
    const int blk = blockIdx.x;
    const int b   = blk / BLOCKS_PER_BATCH;
    const int e0  = (blk % BLOCKS_PER_BATCH) * EBLK;
    const int ebase = b * NE + e0;

    // Stage Wf (32x256 floats = 2048 float4)
    {
        float4* wsh = (float4*)&Wf[0][0];
        const float4* wg = (const float4*)W;
#pragma unroll
        for (int i = 0; i < 8; i++) wsh[t + 256 * i] = wg[t + 256 * i];
    }
    // Stage edge features transposed: efs_t[k][edge]
    {
#pragma unroll
        for (int it = 0; it < 2; it++) {
            int i = t + 256 * it;
            int r = i >> 3;          // edge 0..63
            int c = (i & 7) * 4;     // feature quad
            float4 v = *(const float4*)&ef[(size_t)(ebase + r) * FF + c];
            efs_t[c + 0][r] = v.x; efs_t[c + 1][r] = v.y;
            efs_t[c + 2][r] = v.z; efs_t[c + 3][r] = v.w;
        }
    }
    // Stage indices (normalized int32, clamped)
    if (t < EBLK) {
        src_s[t] = g_src[ebase + t];
        tgt_s[t] = g_tgt[ebase + t];
    }
    __syncthreads();

    const int grp = t >> 6;          // 0..3: which quad-group
    const int m4  = (t & 63) * 4;    // column quad 0..252
    const int nodebase = b * NN;

#pragma unroll 1
    for (int qi = 0; qi < 4; qi++) {
        const int q = qi * 4 + grp;  // edge quad 0..15

        float4 acc0 = make_float4(0.f, 0.f, 0.f, 0.f);
        float4 acc1 = acc0, acc2 = acc0, acc3 = acc0;

#pragma unroll 8
        for (int k = 0; k < FF; k++) {
            float4 a = *(const float4*)&efs_t[k][q * 4];   // 4 edges, feature k (broadcast)
            float4 w = *(const float4*)&Wf[k][m4];         // 4 cols
            acc0.x += a.x * w.x; acc0.y += a.x * w.y; acc0.z += a.x * w.z; acc0.w += a.x * w.w;
            acc1.x += a.y * w.x; acc1.y += a.y * w.y; acc1.z += a.y * w.z; acc1.w += a.y * w.w;
            acc2.x += a.z * w.x; acc2.y += a.z * w.y; acc2.z += a.z * w.z; acc2.w += a.z * w.w;
            acc3.x += a.w * w.x; acc3.y += a.w * w.y; acc3.z += a.w * w.z; acc3.w += a.w * w.w;
        }

        // Epilogue: 4 edges, coalesced gathers + relu + vector reduction
#pragma unroll
        for (int j = 0; j < 4; j++) {
            float4 acc = (j == 0) ? acc0 : (j == 1) ? acc1 : (j == 2) ? acc2 : acc3;
            const int e = q * 4 + j;
            const int s = src_s[e];
            const int d = tgt_s[e];

            float4 ps = *(const float4*)&g_Ps[(size_t)(nodebase + s) * MM + m4];
            float4 pt = *(const float4*)&g_Pt[(size_t)(nodebase + d) * MM + m4];

            float4 r;
            r.x = fmaxf(acc.x + ps.x + pt.x, 0.f);
            r.y = fmaxf(acc.y + ps.y + pt.y, 0.f);
            r.z = fmaxf(acc.z + ps.z + pt.z, 0.f);
            r.w = fmaxf(acc.w + ps.w + pt.w, 0.f);

            float* op = &out[(size_t)(nodebase + d) * MM + m4];
            asm volatile("red.global.add.v4.f32 [%0], {%1, %2, %3, %4};"
                         :: "l"(op), "f"(r.x), "f"(r.y), "f"(r.z), "f"(r.w)
                         : "memory");
        }
    }
}

// ---------------------------------------------------------------------------
// kernel_launch
// Inputs identified BY ELEMENT COUNT (robust to metadata ordering):
//   hidden f32 = 5,120,000 | edge_features f32 = 20,480,000
//   edge_sources = 640,000 | edge_targets = 640,000 (first/second by order)
//   W_msg f32 = 73,728 | b_msg f32 = 256
// Index dtype (int32 vs int64) detected ON DEVICE.
// Output f32 [4,10000,256].
// ---------------------------------------------------------------------------
extern "C" void kernel_launch(void* const* d_in, const int* in_sizes, int n_in,
                              void* d_out, int out_size) {
    const float* hidden = nullptr;
    const float* ef     = nullptr;
    const void*  srcs   = nullptr;
    const void*  tgts   = nullptr;
    const float* W      = nullptr;
    const float* bmsg   = nullptr;

    for (int i = 0; i < n_in; i++) {
        switch (in_sizes[i]) {
            case SZ_HIDDEN: hidden = (const float*)d_in[i]; break;
            case SZ_EF:     ef     = (const float*)d_in[i]; break;
            case SZ_W:      W      = (const float*)d_in[i]; break;
            case SZ_B:      bmsg   = (const float*)d_in[i]; break;
            case SZ_IDX:
                if (!srcs) srcs = d_in[i];
                else       tgts = d_in[i];
                break;
            default: break;
        }
    }
    float* out = (float*)d_out;

    // 0) detect index dtype + normalize to int32 scratch (both arrays, 1 launch)
    detect_idx_kernel<<<1, 32>>>((const int*)srcs, (const int*)tgts);
    convert_idx_kernel<<<(2 * SZ_IDX + 255) / 256, 256>>>(srcs, tgts);

    // 1) zero output (poisoned by harness)
    int n4 = out_size / 4;
    zero_kernel<<<(n4 + 255) / 256, 256>>>((float4*)out, n4);

    // 2) fused node projections: Ps = h @ W[32:160], Pt = h @ W[160:288] + b
    dim3 gA(BN / 64, MM / 64);
    node_proj_kernel<<<gA, 256>>>(hidden,
                                  W + (size_t)FF * MM,
                                  W + (size_t)(FF + HH) * MM,
                                  bmsg);

    // 3) per-edge message + scatter-add
    edge_kernel<<<NB * BLOCKS_PER_BATCH, 256>>>(ef, W, out);
}